// round 1
// baseline (speedup 1.0000x reference)
#include <cuda_runtime.h>
#include <stdint.h>

// Problem constants (fixed shapes from setup_inputs)
#define BATCH   4
#define DDIM    512
#define TQ      4096
#define MROWS   (BATCH * TQ)     // 16384 query rows
#define NCODES  8192

// GEMM tiling
#define BM 128
#define BN 128
#define BK 16
#define BNP 132                   // padded Bs row (multiple of 4 for float4, breaks store conflicts)

// Scratch (no allocations allowed -> device globals)
__device__ unsigned long long g_best[MROWS];
__device__ float g_inv_norm[NCODES];

// Monotonic float -> uint key (total order matching fp32 <)
__device__ __forceinline__ unsigned int fkey(float v) {
    unsigned int u = __float_as_uint(v);
    return (u & 0x80000000u) ? ~u : (u | 0x80000000u);
}

__global__ void init_best_kernel() {
    int i = blockIdx.x * blockDim.x + threadIdx.x;
    if (i < MROWS) g_best[i] = 0ULL;
}

// 1 / max(||emb_n||, 1e-12), one warp per code row
__global__ void inv_norm_kernel(const float* __restrict__ emb) {
    int warp = (blockIdx.x * blockDim.x + threadIdx.x) >> 5;
    int lane = threadIdx.x & 31;
    if (warp >= NCODES) return;
    const float* row = emb + (size_t)warp * DDIM;
    float s = 0.f;
    #pragma unroll
    for (int k = lane; k < DDIM; k += 32) { float v = row[k]; s = fmaf(v, v, s); }
    #pragma unroll
    for (int o = 16; o; o >>= 1) s += __shfl_down_sync(0xffffffffu, s, o);
    if (lane == 0) g_inv_norm[warp] = 1.0f / fmaxf(sqrtf(s), 1e-12f);
}

// Fused GEMM + per-row argmax.
// A[m][k] = z[b][k][t]  (m = b*TQ + t)  -> contiguous in m for fixed k (coalesced)
// B[n][k] = emb[n][k]                   -> contiguous in k (coalesced)
__global__ __launch_bounds__(256, 2)
void argmax_gemm_kernel(const float* __restrict__ z, const float* __restrict__ emb) {
    __shared__ float As[BK][BM];
    __shared__ float Bs[BK][BNP];

    const int tid = threadIdx.x;
    const int tx = tid & 15;        // column group (8 cols each)
    const int ty = tid >> 4;        // row group (8 rows each)

    const int n0 = blockIdx.x * BN;
    const int m0 = blockIdx.y * BM;
    const int bidx = m0 / TQ;       // BM=128 divides TQ=4096, tile never crosses batch
    const int t0 = m0 % TQ;
    const float* zbase = z + (size_t)bidx * DDIM * TQ + t0;

    float acc[8][8];
    #pragma unroll
    for (int i = 0; i < 8; i++)
        #pragma unroll
        for (int j = 0; j < 8; j++) acc[i][j] = 0.f;

    for (int k0 = 0; k0 < DDIM; k0 += BK) {
        // Load A tile: 16 x 128, coalesced in m
        #pragma unroll
        for (int p = 0; p < 8; p++) {
            int idx = p * 256 + tid;
            int k = idx >> 7;       // 0..15
            int m = idx & 127;
            As[k][m] = zbase[(size_t)(k0 + k) * TQ + m];
        }
        // Load B tile: 128 x 16, contiguous in k per code row
        #pragma unroll
        for (int p = 0; p < 8; p++) {
            int idx = p * 256 + tid;
            int n = idx >> 4;       // 0..127
            int k = idx & 15;
            Bs[k][n] = emb[(size_t)(n0 + n) * DDIM + (k0 + k)];
        }
        __syncthreads();

        #pragma unroll
        for (int kk = 0; kk < BK; kk++) {
            float a[8], bv[8];
            const float4* ap = (const float4*)&As[kk][ty * 8];
            float4 a0 = ap[0], a1 = ap[1];
            a[0]=a0.x; a[1]=a0.y; a[2]=a0.z; a[3]=a0.w;
            a[4]=a1.x; a[5]=a1.y; a[6]=a1.z; a[7]=a1.w;
            const float4* bp = (const float4*)&Bs[kk][tx * 8];
            float4 b0 = bp[0], b1 = bp[1];
            bv[0]=b0.x; bv[1]=b0.y; bv[2]=b0.z; bv[3]=b0.w;
            bv[4]=b1.x; bv[5]=b1.y; bv[6]=b1.z; bv[7]=b1.w;
            #pragma unroll
            for (int i = 0; i < 8; i++)
                #pragma unroll
                for (int j = 0; j < 8; j++)
                    acc[i][j] = fmaf(a[i], bv[j], acc[i][j]);
        }
        __syncthreads();
    }

    // Epilogue: cosine scale + argmax, tie-break = smallest index (matches jnp.argmax)
    float invn[8];
    #pragma unroll
    for (int j = 0; j < 8; j++) invn[j] = g_inv_norm[n0 + tx * 8 + j];

    #pragma unroll
    for (int i = 0; i < 8; i++) {
        unsigned long long best = 0ULL;
        #pragma unroll
        for (int j = 0; j < 8; j++) {
            int n = n0 + tx * 8 + j;
            float v = acc[i][j] * invn[j];
            unsigned long long p = ((unsigned long long)fkey(v) << 32)
                                 | (unsigned long long)(0xFFFFFFFFu - (unsigned)n);
            best = (p > best) ? p : best;
        }
        // reduce across the 16 tx lanes sharing this row
        #pragma unroll
        for (int o = 8; o; o >>= 1) {
            unsigned long long other = __shfl_down_sync(0xffffffffu, best, o, 16);
            best = (other > best) ? other : best;
        }
        if (tx == 0)
            atomicMax(&g_best[m0 + ty * 8 + i], best);
    }
}

// Gather + transpose: out = [z_q_st (B*D*TQ)] [idx as float (B*TQ)] [z_q (B*D*TQ)]
// out[b][c][t] = emb[idx[b*TQ+t]][c]; z_q_st reproduces fp32 z + (z_q - z).
__global__ __launch_bounds__(256)
void gather_kernel(const float* __restrict__ z, const float* __restrict__ emb,
                   float* __restrict__ out) {
    __shared__ float tile[32][33];
    __shared__ int sidx[32];

    const int r0 = blockIdx.x * 32;          // 32 consecutive rows (same batch: 32 | 4096)
    const int tid = threadIdx.x;
    const int tx = tid & 31;
    const int tyw = tid >> 5;                 // 0..7

    if (tid < 32) {
        unsigned long long p = g_best[r0 + tid];
        int n = (int)(0xFFFFFFFFu - (unsigned)(p & 0xFFFFFFFFu));
        sidx[tid] = n;
        out[(size_t)BATCH * DDIM * TQ + r0 + tid] = (float)n;  // idx output
    }
    __syncthreads();

    const int b = r0 / TQ;
    const int t0 = r0 % TQ;
    float* out_st = out;
    float* out_q  = out + (size_t)BATCH * DDIM * TQ + MROWS;

    for (int cc = 0; cc < DDIM; cc += 32) {
        #pragma unroll
        for (int i = 0; i < 4; i++) {
            int row = tyw + i * 8;                          // local t
            tile[row][tx] = emb[(size_t)sidx[row] * DDIM + cc + tx];
        }
        __syncthreads();
        #pragma unroll
        for (int i = 0; i < 4; i++) {
            int c = cc + tyw + i * 8;
            size_t o = ((size_t)b * DDIM + c) * TQ + t0 + tx;   // coalesced in t
            float v = tile[tx][tyw + i * 8];
            out_q[o] = v;
            float zz = z[o];                                    // same layout as output
            out_st[o] = zz + (v - zz);                          // exact ST expression
        }
        __syncthreads();
    }
}

extern "C" void kernel_launch(void* const* d_in, const int* in_sizes, int n_in,
                              void* d_out, int out_size) {
    const float* z   = (const float*)d_in[0];   // [4, 512, 4096]
    const float* emb = (const float*)d_in[1];   // [8192, 512]
    float* out = (float*)d_out;

    init_best_kernel<<<MROWS / 256, 256>>>();
    inv_norm_kernel<<<NCODES / 8, 256>>>(emb);

    dim3 grid(NCODES / BN, MROWS / BM);
    argmax_gemm_kernel<<<grid, 256>>>(z, emb);

    gather_kernel<<<MROWS / 32, 256>>>(z, emb, out);
}

// round 3
// speedup vs baseline: 1.0061x; 1.0061x over previous
#include <cuda_runtime.h>
#include <cuda_bf16.h>
#include <stdint.h>

// ---------------- Problem constants ----------------
#define BATCH   4
#define DDIM    512
#define TQ      4096
#define MROWS   (BATCH * TQ)      // 16384
#define NCODES  8192

// ---------------- GEMM tiling ----------------
#define BM 128
#define BN 128
#define BK 32
#define NBLK   (NCODES / BN)      // 64 n-blocks
#define NSTAGE (DDIM / BK)        // 16 k-stages

// SMEM stage layout (bytes). Row pitch 80B (32 bf16 data + 8 pad) -> ldmatrix conflict-free.
#define ROWPITCH 80
#define AMAT  (128 * ROWPITCH)    // 10240 per matrix (hi or lo)
#define A_HI  0
#define A_LO  AMAT
#define B_HI  (2 * AMAT)
#define B_LO  (3 * AMAT)
#define STAGE (4 * AMAT)          // 40960
#define SMEM_GEMM (2 * STAGE)     // 81920

#define MARGIN_THRESH 6e-3f       // flag threshold (abs, unnormalized-z scale)

// ---------------- Device scratch (no runtime allocation allowed) ----------------
__device__ __nv_bfloat16 g_zhi[(size_t)MROWS * DDIM];
__device__ __nv_bfloat16 g_zlo[(size_t)MROWS * DDIM];
__device__ __nv_bfloat16 g_ehi[(size_t)NCODES * DDIM];
__device__ __nv_bfloat16 g_elo[(size_t)NCODES * DDIM];
__device__ float g_inv_norm[NCODES];
__device__ unsigned long long g_tiletop2[(size_t)MROWS * NBLK * 2];  // 16MB
__device__ unsigned long long g_best[MROWS];
__device__ int g_flagged[MROWS];
__device__ int g_nflag;

// ---------------- helpers ----------------
__device__ __forceinline__ uint32_t smem_u32(const void* p) {
    uint32_t a;
    asm("{ .reg .u64 t; cvta.to.shared.u64 t, %1; cvt.u32.u64 %0, t; }" : "=r"(a) : "l"(p));
    return a;
}
__device__ __forceinline__ void cpasync16(uint32_t dst, const void* src) {
    asm volatile("cp.async.cg.shared.global [%0], [%1], 16;" :: "r"(dst), "l"(src) : "memory");
}
#define CP_COMMIT() asm volatile("cp.async.commit_group;" ::: "memory")
#define CP_WAIT(n)  asm volatile("cp.async.wait_group %0;" :: "n"(n) : "memory")

#define LDSM4(R, addr) \
    asm volatile("ldmatrix.sync.aligned.m8n8.x4.shared.b16 {%0,%1,%2,%3}, [%4];" \
                 : "=r"((R)[0]), "=r"((R)[1]), "=r"((R)[2]), "=r"((R)[3]) : "r"(addr))

#define MMA_BF16(C, A, b0v, b1v) \
    asm volatile("mma.sync.aligned.m16n8k16.row.col.f32.bf16.bf16.f32 " \
                 "{%0,%1,%2,%3}, {%4,%5,%6,%7}, {%8,%9}, {%0,%1,%2,%3};" \
                 : "+f"((C)[0]), "+f"((C)[1]), "+f"((C)[2]), "+f"((C)[3]) \
                 : "r"((A)[0]), "r"((A)[1]), "r"((A)[2]), "r"((A)[3]), "r"(b0v), "r"(b1v))

// Monotonic float key (total order matching fp32 <)
__device__ __forceinline__ unsigned int fkey(float v) {
    unsigned int u = __float_as_uint(v);
    return (u & 0x80000000u) ? ~u : (u | 0x80000000u);
}
__device__ __forceinline__ float unkey(unsigned int k) {
    unsigned int u = (k & 0x80000000u) ? (k ^ 0x80000000u) : ~k;
    return __uint_as_float(u);
}
__device__ __forceinline__ unsigned long long pack_key(float v, int n) {
    return ((unsigned long long)fkey(v) << 32) | (unsigned long long)(0xFFFFFFFFu - (unsigned)n);
}
// merge pair (o1>=o2) into (b1>=b2)
__device__ __forceinline__ void merge2(unsigned long long& b1, unsigned long long& b2,
                                       unsigned long long o1, unsigned long long o2) {
    if (o1 > b1) { b2 = (b1 > o2) ? b1 : o2; b1 = o1; }
    else if (o1 > b2) { b2 = o1; }
}

// ---------------- Small kernels ----------------
__global__ void init_flag_kernel() { g_nflag = 0; }

__global__ void inv_norm_kernel(const float* __restrict__ emb) {
    int warp = (blockIdx.x * blockDim.x + threadIdx.x) >> 5;
    int lane = threadIdx.x & 31;
    if (warp >= NCODES) return;
    const float* row = emb + (size_t)warp * DDIM;
    float s = 0.f;
    #pragma unroll
    for (int k = lane; k < DDIM; k += 32) { float v = row[k]; s = fmaf(v, v, s); }
    #pragma unroll
    for (int o = 16; o; o >>= 1) s += __shfl_down_sync(0xffffffffu, s, o);
    if (lane == 0) g_inv_norm[warp] = 1.0f / fmaxf(sqrtf(s), 1e-12f);
}

// Codes: fold inv_norm, split to bf16 hi/lo (already [n][k] row-major)
__global__ __launch_bounds__(256) void split_e_kernel(const float* __restrict__ emb) {
    int i = blockIdx.x * 256 + threadIdx.x;
    float v = emb[i] * g_inv_norm[i >> 9];
    __nv_bfloat16 h = __float2bfloat16(v);
    g_ehi[i] = h;
    g_elo[i] = __float2bfloat16(v - __bfloat162float(h));
}

// Queries: transpose [b][k][t] -> A[m=b*TQ+t][k], split to bf16 hi/lo
__global__ __launch_bounds__(256) void split_z_kernel(const float* __restrict__ z) {
    __shared__ float tile[32][33];
    int b  = blockIdx.z;
    int k0 = blockIdx.y * 32;
    int t0 = blockIdx.x * 32;
    int tx = threadIdx.x & 31, ty = threadIdx.x >> 5;
    #pragma unroll
    for (int i = 0; i < 4; i++) {
        int kl = ty + i * 8;
        tile[kl][tx] = z[((size_t)b * DDIM + k0 + kl) * TQ + t0 + tx];
    }
    __syncthreads();
    #pragma unroll
    for (int i = 0; i < 4; i++) {
        int tl = ty + i * 8;
        int m = b * TQ + t0 + tl;
        float v = tile[tx][tl];
        __nv_bfloat16 h = __float2bfloat16(v);
        size_t o = (size_t)m * DDIM + k0 + tx;
        g_zhi[o] = h;
        g_zlo[o] = __float2bfloat16(v - __bfloat162float(h));
    }
}

// ---------------- Main GEMM + per-tile top2 ----------------
__device__ __forceinline__ void load_stage(uint32_t sbase, int tid, int m0, int n0, int k0) {
    #pragma unroll
    for (int it = 0; it < 2; it++) {
        int c = it * 256 + tid;
        int row = c >> 2, col = c & 3;
        uint32_t d = sbase + (uint32_t)(row * ROWPITCH + col * 16);
        size_t gofs = ((size_t)(m0 + row) * DDIM + k0) * 2 + col * 16;
        cpasync16(d,        (const char*)g_zhi + gofs);
        cpasync16(d + AMAT, (const char*)g_zlo + gofs);
    }
    #pragma unroll
    for (int it = 0; it < 2; it++) {
        int c = it * 256 + tid;
        int row = c >> 2, col = c & 3;
        uint32_t d = sbase + B_HI + (uint32_t)(row * ROWPITCH + col * 16);
        size_t gofs = ((size_t)(n0 + row) * DDIM + k0) * 2 + col * 16;
        cpasync16(d,        (const char*)g_ehi + gofs);
        cpasync16(d + AMAT, (const char*)g_elo + gofs);
    }
}

__global__ __launch_bounds__(256, 1)
void gemm_argmax_kernel() {
    extern __shared__ char smem[];
    uint32_t sb = smem_u32(smem);
    const int tid = threadIdx.x;
    const int w = tid >> 5, l = tid & 31;
    const int wy = w >> 2, wx = w & 3;       // warp grid: 2 (M) x 4 (N)
    const int m0 = blockIdx.y * BM;
    const int n0 = blockIdx.x * BN;

    float c[4][4][4];
    #pragma unroll
    for (int i = 0; i < 4; i++)
        #pragma unroll
        for (int j = 0; j < 4; j++)
            #pragma unroll
            for (int r = 0; r < 4; r++) c[i][j][r] = 0.f;

    // per-thread ldmatrix base addresses (within stage 0, A_HI / B_HI)
    const uint32_t aBase = sb + (uint32_t)((wy * 64 + (l & 15)) * ROWPITCH + ((l >> 4) << 4));
    const uint32_t bBase = sb + B_HI +
        (uint32_t)((wx * 32 + ((l >> 4) & 1) * 8 + (l & 7)) * ROWPITCH + ((l >> 3) & 1) * 16);

    load_stage(sb, tid, m0, n0, 0);
    CP_COMMIT();

    #pragma unroll 1
    for (int s = 0; s < NSTAGE; s++) {
        if (s > 0) __syncthreads();   // compute(s-1) done before overwriting its buffer
        if (s + 1 < NSTAGE) {
            load_stage(sb + ((s + 1) & 1) * STAGE, tid, m0, n0, (s + 1) * BK);
            CP_COMMIT();
            CP_WAIT(1);
        } else {
            CP_WAIT(0);
        }
        __syncthreads();

        const uint32_t so = (uint32_t)((s & 1) * STAGE);
        #pragma unroll
        for (int ks = 0; ks < 2; ks++) {
            uint32_t ah[4][4], al[4][4];
            #pragma unroll
            for (int mi = 0; mi < 4; mi++) {
                uint32_t aa = aBase + so + (uint32_t)(mi * 16 * ROWPITCH + ks * 32);
                LDSM4(ah[mi], aa);
                LDSM4(al[mi], aa + AMAT);
            }
            uint32_t bh[2][4], bl[2][4];
            #pragma unroll
            for (int np = 0; np < 2; np++) {
                uint32_t ba = bBase + so + (uint32_t)(np * 16 * ROWPITCH + ks * 32);
                LDSM4(bh[np], ba);
                LDSM4(bl[np], ba + AMAT);
            }
            #pragma unroll
            for (int mi = 0; mi < 4; mi++)
                #pragma unroll
                for (int ni = 0; ni < 4; ni++) {
                    int np = ni >> 1, q = (ni & 1) * 2;
                    MMA_BF16(c[mi][ni], ah[mi], bh[np][q], bh[np][q + 1]);   // hi*hi
                    MMA_BF16(c[mi][ni], ah[mi], bl[np][q], bl[np][q + 1]);   // hi*lo
                    MMA_BF16(c[mi][ni], al[mi], bh[np][q], bh[np][q + 1]);   // lo*hi
                }
        }
    }

    // -------- epilogue: per-row top2 within CTA --------
    __syncthreads();  // smem stages no longer needed; reuse for reduction
    unsigned long long* stop2 = (unsigned long long*)smem;  // [128][4][2]

    #pragma unroll
    for (int mi = 0; mi < 4; mi++) {
        #pragma unroll
        for (int half = 0; half < 2; half++) {
            unsigned long long b1 = 0ULL, b2 = 0ULL;
            #pragma unroll
            for (int ni = 0; ni < 4; ni++) {
                #pragma unroll
                for (int r = 0; r < 2; r++) {
                    float v = c[mi][ni][half * 2 + r];
                    int n = n0 + wx * 32 + ni * 8 + ((l & 3) << 1) + r;
                    unsigned long long key = pack_key(v, n);
                    if (key > b1) { b2 = b1; b1 = key; }
                    else if (key > b2) { b2 = key; }
                }
            }
            #pragma unroll
            for (int off = 1; off < 4; off <<= 1) {
                unsigned long long o1 = __shfl_xor_sync(0xffffffffu, b1, off);
                unsigned long long o2 = __shfl_xor_sync(0xffffffffu, b2, off);
                merge2(b1, b2, o1, o2);
            }
            if ((l & 3) == 0) {
                int rl = wy * 64 + mi * 16 + half * 8 + (l >> 2);
                stop2[(rl * 4 + wx) * 2 + 0] = b1;
                stop2[(rl * 4 + wx) * 2 + 1] = b2;
            }
        }
    }
    __syncthreads();

    if (tid < 128) {
        unsigned long long b1 = stop2[(tid * 4) * 2], b2 = stop2[(tid * 4) * 2 + 1];
        #pragma unroll
        for (int x = 1; x < 4; x++)
            merge2(b1, b2, stop2[(tid * 4 + x) * 2], stop2[(tid * 4 + x) * 2 + 1]);
        size_t o = ((size_t)(m0 + tid) * NBLK + blockIdx.x) * 2;
        g_tiletop2[o] = b1;
        g_tiletop2[o + 1] = b2;
    }
}

// ---------------- Merge tiles per row, flag narrow margins ----------------
__global__ __launch_bounds__(256) void merge_flag_kernel() {
    int warp = (blockIdx.x * 256 + threadIdx.x) >> 5;
    int l = threadIdx.x & 31;
    if (warp >= MROWS) return;
    const unsigned long long* t = &g_tiletop2[(size_t)warp * NBLK * 2];
    unsigned long long b1 = t[l * 2], b2 = t[l * 2 + 1];
    merge2(b1, b2, t[(l + 32) * 2], t[(l + 32) * 2 + 1]);
    #pragma unroll
    for (int off = 16; off; off >>= 1) {
        unsigned long long o1 = __shfl_down_sync(0xffffffffu, b1, off);
        unsigned long long o2 = __shfl_down_sync(0xffffffffu, b2, off);
        merge2(b1, b2, o1, o2);
    }
    if (l == 0) {
        g_best[warp] = b1;
        float v1 = unkey((unsigned)(b1 >> 32));
        float v2 = unkey((unsigned)(b2 >> 32));
        if (v1 - v2 < MARGIN_THRESH) {
            int p = atomicAdd(&g_nflag, 1);
            g_flagged[p] = warp;
        }
    }
}

// ---------------- Exact fp32 rescore of flagged rows ----------------
__global__ __launch_bounds__(256) void fallback_kernel(const float* __restrict__ z,
                                                       const float* __restrict__ emb) {
    __shared__ float zv[DDIM];
    __shared__ unsigned long long wbest[8];
    int tid = threadIdx.x, wid = tid >> 5, lane = tid & 31;
    int nf = g_nflag;
    for (int i = blockIdx.x; i < nf; i += gridDim.x) {
        int m = g_flagged[i];
        int b = m >> 12, t = m & (TQ - 1);
        for (int k = tid; k < DDIM; k += 256)
            zv[k] = z[((size_t)b * DDIM + k) * TQ + t];
        __syncthreads();
        unsigned long long best = 0ULL;
        for (int n = wid; n < NCODES; n += 8) {
            const float* er = emb + (size_t)n * DDIM;
            float s = 0.f;
            #pragma unroll
            for (int k = lane; k < DDIM; k += 32) s = fmaf(zv[k], er[k], s);
            #pragma unroll
            for (int o = 16; o; o >>= 1) s += __shfl_down_sync(0xffffffffu, s, o);
            if (lane == 0) {
                s *= g_inv_norm[n];
                unsigned long long key = pack_key(s, n);
                if (key > best) best = key;
            }
        }
        if (lane == 0) wbest[wid] = best;
        __syncthreads();
        if (tid == 0) {
            unsigned long long bb = wbest[0];
            #pragma unroll
            for (int w = 1; w < 8; w++) if (wbest[w] > bb) bb = wbest[w];
            g_best[m] = bb;
        }
        __syncthreads();
    }
}

// ---------------- Gather + outputs ----------------
__global__ __launch_bounds__(256)
void gather_kernel(const float* __restrict__ z, const float* __restrict__ emb,
                   float* __restrict__ out) {
    __shared__ float tile[32][33];
    __shared__ int sidx[32];

    const int r0 = blockIdx.x * 32;
    const int tid = threadIdx.x;
    const int tx = tid & 31;
    const int tyw = tid >> 5;

    if (tid < 32) {
        unsigned long long p = g_best[r0 + tid];
        int n = (int)(0xFFFFFFFFu - (unsigned)(p & 0xFFFFFFFFu));
        sidx[tid] = n;
        out[(size_t)BATCH * DDIM * TQ + r0 + tid] = (float)n;
    }
    __syncthreads();

    const int b = r0 / TQ;
    const int t0 = r0 % TQ;
    float* out_st = out;
    float* out_q  = out + (size_t)BATCH * DDIM * TQ + MROWS;

    for (int cc = 0; cc < DDIM; cc += 32) {
        #pragma unroll
        for (int i = 0; i < 4; i++) {
            int row = tyw + i * 8;
            tile[row][tx] = emb[(size_t)sidx[row] * DDIM + cc + tx];
        }
        __syncthreads();
        #pragma unroll
        for (int i = 0; i < 4; i++) {
            int cidx = cc + tyw + i * 8;
            size_t o = ((size_t)b * DDIM + cidx) * TQ + t0 + tx;
            float v = tile[tx][tyw + i * 8];
            out_q[o] = v;
            float zz = z[o];
            out_st[o] = zz + (v - zz);
        }
        __syncthreads();
    }
}

// ---------------- Launch ----------------
extern "C" void kernel_launch(void* const* d_in, const int* in_sizes, int n_in,
                              void* d_out, int out_size) {
    const float* z   = (const float*)d_in[0];   // [4, 512, 4096]
    const float* emb = (const float*)d_in[1];   // [8192, 512]
    float* out = (float*)d_out;

    static int smem_set = 0;
    if (!smem_set) {
        cudaFuncSetAttribute(gemm_argmax_kernel,
                             cudaFuncAttributeMaxDynamicSharedMemorySize, SMEM_GEMM);
        smem_set = 1;
    }

    init_flag_kernel<<<1, 1>>>();
    inv_norm_kernel<<<NCODES / 8, 256>>>(emb);
    split_e_kernel<<<(NCODES * DDIM) / 256, 256>>>(emb);
    split_z_kernel<<<dim3(TQ / 32, DDIM / 32, BATCH), 256>>>(z);

    gemm_argmax_kernel<<<dim3(NBLK, MROWS / BM), 256, SMEM_GEMM>>>();

    merge_flag_kernel<<<(MROWS * 32) / 256, 256>>>();
    fallback_kernel<<<256, 256>>>(z, emb);
    gather_kernel<<<MROWS / 32, 256>>>(z, emb, out);
}

// round 4
// speedup vs baseline: 1.3811x; 1.3727x over previous
#include <cuda_runtime.h>
#include <cuda_fp16.h>
#include <stdint.h>

// ---------------- Problem constants ----------------
#define BATCH   4
#define DDIM    512
#define TQ      4096
#define MROWS   (BATCH * TQ)      // 16384
#define NCODES  8192

// ---------------- GEMM tiling ----------------
#define BM 128
#define BN 128
#define BK 32
#define NBLK   (NCODES / BN)      // 64 n-blocks
#define NSTAGE (DDIM / BK)        // 16 k-stages

// SMEM: row pitch 80B (64B data = 32 fp16 + 16 pad) -> ldmatrix conflict-free
#define ROWPITCH 80
#define AMAT  (128 * ROWPITCH)    // 10240 bytes per matrix
#define B_OFF AMAT
#define STAGE (2 * AMAT)          // 20480
#define SMEM_GEMM (2 * STAGE)     // 40960 (fits default 48KB static)

#define MARGIN_THRESH 0.012f      // ~17 sigma of fp16 screening error diff

// ---------------- Device scratch ----------------
__device__ __half g_zh[(size_t)MROWS * DDIM];
__device__ __half g_eh[(size_t)NCODES * DDIM];
__device__ float g_inv_norm[NCODES];
__device__ unsigned long long g_tiletop2[(size_t)MROWS * NBLK * 2];  // 16MB
__device__ unsigned long long g_best[MROWS];
__device__ int g_flagged[MROWS];
__device__ int g_nflag;

// ---------------- helpers ----------------
__device__ __forceinline__ uint32_t smem_u32(const void* p) {
    uint32_t a;
    asm("{ .reg .u64 t; cvta.to.shared.u64 t, %1; cvt.u32.u64 %0, t; }" : "=r"(a) : "l"(p));
    return a;
}
__device__ __forceinline__ void cpasync16(uint32_t dst, const void* src) {
    asm volatile("cp.async.cg.shared.global [%0], [%1], 16;" :: "r"(dst), "l"(src) : "memory");
}
#define CP_COMMIT() asm volatile("cp.async.commit_group;" ::: "memory")
#define CP_WAIT(n)  asm volatile("cp.async.wait_group %0;" :: "n"(n) : "memory")

#define LDSM4(R, addr) \
    asm volatile("ldmatrix.sync.aligned.m8n8.x4.shared.b16 {%0,%1,%2,%3}, [%4];" \
                 : "=r"((R)[0]), "=r"((R)[1]), "=r"((R)[2]), "=r"((R)[3]) : "r"(addr))

#define MMA_F16(C, A, b0v, b1v) \
    asm volatile("mma.sync.aligned.m16n8k16.row.col.f32.f16.f16.f32 " \
                 "{%0,%1,%2,%3}, {%4,%5,%6,%7}, {%8,%9}, {%0,%1,%2,%3};" \
                 : "+f"((C)[0]), "+f"((C)[1]), "+f"((C)[2]), "+f"((C)[3]) \
                 : "r"((A)[0]), "r"((A)[1]), "r"((A)[2]), "r"((A)[3]), "r"(b0v), "r"(b1v))

__device__ __forceinline__ unsigned int fkey(float v) {
    unsigned int u = __float_as_uint(v);
    return (u & 0x80000000u) ? ~u : (u | 0x80000000u);
}
__device__ __forceinline__ float unkey(unsigned int k) {
    unsigned int u = (k & 0x80000000u) ? (k ^ 0x80000000u) : ~k;
    return __uint_as_float(u);
}
__device__ __forceinline__ unsigned long long pack_key(float v, int n) {
    return ((unsigned long long)fkey(v) << 32) | (unsigned long long)(0xFFFFFFFFu - (unsigned)n);
}
__device__ __forceinline__ void merge2(unsigned long long& b1, unsigned long long& b2,
                                       unsigned long long o1, unsigned long long o2) {
    if (o1 > b1) { b2 = (b1 > o2) ? b1 : o2; b1 = o1; }
    else if (o1 > b2) { b2 = o1; }
}

// ---------------- Small kernels ----------------
__global__ void init_flag_kernel() { g_nflag = 0; }

__global__ void inv_norm_kernel(const float* __restrict__ emb) {
    int warp = (blockIdx.x * blockDim.x + threadIdx.x) >> 5;
    int lane = threadIdx.x & 31;
    if (warp >= NCODES) return;
    const float* row = emb + (size_t)warp * DDIM;
    float s = 0.f;
    #pragma unroll
    for (int k = lane; k < DDIM; k += 32) { float v = row[k]; s = fmaf(v, v, s); }
    #pragma unroll
    for (int o = 16; o; o >>= 1) s += __shfl_down_sync(0xffffffffu, s, o);
    if (lane == 0) g_inv_norm[warp] = 1.0f / fmaxf(sqrtf(s), 1e-12f);
}

// Codes: fold inv_norm, convert to fp16 (already [n][k] row-major)
__global__ __launch_bounds__(256) void conv_e_kernel(const float* __restrict__ emb) {
    int i = blockIdx.x * 256 + threadIdx.x;
    g_eh[i] = __float2half(emb[i] * g_inv_norm[i >> 9]);
}

// Queries: transpose [b][k][t] -> A[m=b*TQ+t][k] fp16
__global__ __launch_bounds__(256) void conv_z_kernel(const float* __restrict__ z) {
    __shared__ float tile[32][33];
    int b  = blockIdx.z;
    int k0 = blockIdx.y * 32;
    int t0 = blockIdx.x * 32;
    int tx = threadIdx.x & 31, ty = threadIdx.x >> 5;
    #pragma unroll
    for (int i = 0; i < 4; i++) {
        int kl = ty + i * 8;
        tile[kl][tx] = z[((size_t)b * DDIM + k0 + kl) * TQ + t0 + tx];
    }
    __syncthreads();
    #pragma unroll
    for (int i = 0; i < 4; i++) {
        int tl = ty + i * 8;
        int m = b * TQ + t0 + tl;
        g_zh[(size_t)m * DDIM + k0 + tx] = __float2half(tile[tx][tl]);
    }
}

// ---------------- Main GEMM + per-tile top2 ----------------
__device__ __forceinline__ void load_stage(uint32_t sbase, int tid, int m0, int n0, int k0) {
    #pragma unroll
    for (int it = 0; it < 2; it++) {
        int c = it * 256 + tid;
        int row = c >> 2, col = c & 3;
        size_t gofs = ((size_t)(m0 + row) * DDIM + k0) * 2 + col * 16;
        cpasync16(sbase + (uint32_t)(row * ROWPITCH + col * 16),
                  (const char*)g_zh + gofs);
    }
    #pragma unroll
    for (int it = 0; it < 2; it++) {
        int c = it * 256 + tid;
        int row = c >> 2, col = c & 3;
        size_t gofs = ((size_t)(n0 + row) * DDIM + k0) * 2 + col * 16;
        cpasync16(sbase + B_OFF + (uint32_t)(row * ROWPITCH + col * 16),
                  (const char*)g_eh + gofs);
    }
}

__global__ __launch_bounds__(256, 2)
void gemm_argmax_kernel() {
    __shared__ char smem[SMEM_GEMM];
    uint32_t sb = smem_u32(smem);
    const int tid = threadIdx.x;
    const int w = tid >> 5, l = tid & 31;
    const int wy = w >> 2, wx = w & 3;       // warp grid: 2 (M) x 4 (N)
    const int m0 = blockIdx.y * BM;
    const int n0 = blockIdx.x * BN;

    float c[4][4][4];
    #pragma unroll
    for (int i = 0; i < 4; i++)
        #pragma unroll
        for (int j = 0; j < 4; j++)
            #pragma unroll
            for (int r = 0; r < 4; r++) c[i][j][r] = 0.f;

    const uint32_t aBase = sb + (uint32_t)((wy * 64 + (l & 15)) * ROWPITCH + ((l >> 4) << 4));
    const uint32_t bBase = sb + B_OFF +
        (uint32_t)((wx * 32 + ((l >> 4) & 1) * 8 + (l & 7)) * ROWPITCH + ((l >> 3) & 1) * 16);

    load_stage(sb, tid, m0, n0, 0);
    CP_COMMIT();

    #pragma unroll 1
    for (int s = 0; s < NSTAGE; s++) {
        if (s > 0) __syncthreads();
        if (s + 1 < NSTAGE) {
            load_stage(sb + ((s + 1) & 1) * STAGE, tid, m0, n0, (s + 1) * BK);
            CP_COMMIT();
            CP_WAIT(1);
        } else {
            CP_WAIT(0);
        }
        __syncthreads();

        const uint32_t so = (uint32_t)((s & 1) * STAGE);
        #pragma unroll
        for (int ks = 0; ks < 2; ks++) {
            uint32_t ah[4][4];
            #pragma unroll
            for (int mi = 0; mi < 4; mi++)
                LDSM4(ah[mi], aBase + so + (uint32_t)(mi * 16 * ROWPITCH + ks * 32));
            uint32_t bh[2][4];
            #pragma unroll
            for (int np = 0; np < 2; np++)
                LDSM4(bh[np], bBase + so + (uint32_t)(np * 16 * ROWPITCH + ks * 32));
            #pragma unroll
            for (int mi = 0; mi < 4; mi++)
                #pragma unroll
                for (int ni = 0; ni < 4; ni++) {
                    int np = ni >> 1, q = (ni & 1) * 2;
                    MMA_F16(c[mi][ni], ah[mi], bh[np][q], bh[np][q + 1]);
                }
        }
    }

    // -------- epilogue: per-row top2 within CTA --------
    __syncthreads();
    unsigned long long* stop2 = (unsigned long long*)smem;  // [128][4][2]

    #pragma unroll
    for (int mi = 0; mi < 4; mi++) {
        #pragma unroll
        for (int half = 0; half < 2; half++) {
            unsigned long long b1 = 0ULL, b2 = 0ULL;
            #pragma unroll
            for (int ni = 0; ni < 4; ni++) {
                #pragma unroll
                for (int r = 0; r < 2; r++) {
                    float v = c[mi][ni][half * 2 + r];
                    int n = n0 + wx * 32 + ni * 8 + ((l & 3) << 1) + r;
                    unsigned long long key = pack_key(v, n);
                    if (key > b1) { b2 = b1; b1 = key; }
                    else if (key > b2) { b2 = key; }
                }
            }
            #pragma unroll
            for (int off = 1; off < 4; off <<= 1) {
                unsigned long long o1 = __shfl_xor_sync(0xffffffffu, b1, off);
                unsigned long long o2 = __shfl_xor_sync(0xffffffffu, b2, off);
                merge2(b1, b2, o1, o2);
            }
            if ((l & 3) == 0) {
                int rl = wy * 64 + mi * 16 + half * 8 + (l >> 2);
                stop2[(rl * 4 + wx) * 2 + 0] = b1;
                stop2[(rl * 4 + wx) * 2 + 1] = b2;
            }
        }
    }
    __syncthreads();

    if (tid < 128) {
        unsigned long long b1 = stop2[(tid * 4) * 2], b2 = stop2[(tid * 4) * 2 + 1];
        #pragma unroll
        for (int x = 1; x < 4; x++)
            merge2(b1, b2, stop2[(tid * 4 + x) * 2], stop2[(tid * 4 + x) * 2 + 1]);
        size_t o = ((size_t)(m0 + tid) * NBLK + blockIdx.x) * 2;
        g_tiletop2[o] = b1;
        g_tiletop2[o + 1] = b2;
    }
}

// ---------------- Merge tiles per row, flag narrow margins ----------------
__global__ __launch_bounds__(256) void merge_flag_kernel() {
    int warp = (blockIdx.x * 256 + threadIdx.x) >> 5;
    int l = threadIdx.x & 31;
    if (warp >= MROWS) return;
    const unsigned long long* t = &g_tiletop2[(size_t)warp * NBLK * 2];
    unsigned long long b1 = t[l * 2], b2 = t[l * 2 + 1];
    merge2(b1, b2, t[(l + 32) * 2], t[(l + 32) * 2 + 1]);
    #pragma unroll
    for (int off = 16; off; off >>= 1) {
        unsigned long long o1 = __shfl_down_sync(0xffffffffu, b1, off);
        unsigned long long o2 = __shfl_down_sync(0xffffffffu, b2, off);
        merge2(b1, b2, o1, o2);
    }
    if (l == 0) {
        g_best[warp] = b1;
        float v1 = unkey((unsigned)(b1 >> 32));
        float v2 = unkey((unsigned)(b2 >> 32));
        if (v1 - v2 < MARGIN_THRESH) {
            int p = atomicAdd(&g_nflag, 1);
            g_flagged[p] = warp;
        }
    }
}

// ---------------- Exact fp32 rescore of flagged rows ----------------
__global__ __launch_bounds__(256) void fallback_kernel(const float* __restrict__ z,
                                                       const float* __restrict__ emb) {
    __shared__ float zv[DDIM];
    __shared__ unsigned long long wbest[8];
    int tid = threadIdx.x, wid = tid >> 5, lane = tid & 31;
    int nf = g_nflag;
    for (int i = blockIdx.x; i < nf; i += gridDim.x) {
        int m = g_flagged[i];
        int b = m >> 12, t = m & (TQ - 1);
        for (int k = tid; k < DDIM; k += 256)
            zv[k] = z[((size_t)b * DDIM + k) * TQ + t];
        __syncthreads();
        unsigned long long best = 0ULL;
        for (int n = wid; n < NCODES; n += 8) {
            const float* er = emb + (size_t)n * DDIM;
            float s = 0.f;
            #pragma unroll
            for (int k = lane; k < DDIM; k += 32) s = fmaf(zv[k], er[k], s);
            #pragma unroll
            for (int o = 16; o; o >>= 1) s += __shfl_down_sync(0xffffffffu, s, o);
            if (lane == 0) {
                s *= g_inv_norm[n];
                unsigned long long key = pack_key(s, n);
                if (key > best) best = key;
            }
        }
        if (lane == 0) wbest[wid] = best;
        __syncthreads();
        if (tid == 0) {
            unsigned long long bb = wbest[0];
            #pragma unroll
            for (int w = 1; w < 8; w++) if (wbest[w] > bb) bb = wbest[w];
            g_best[m] = bb;
        }
        __syncthreads();
    }
}

// ---------------- Gather + outputs ----------------
__global__ __launch_bounds__(256)
void gather_kernel(const float* __restrict__ z, const float* __restrict__ emb,
                   float* __restrict__ out) {
    __shared__ float tile[32][33];
    __shared__ int sidx[32];

    const int r0 = blockIdx.x * 32;
    const int tid = threadIdx.x;
    const int tx = tid & 31;
    const int tyw = tid >> 5;

    if (tid < 32) {
        unsigned long long p = g_best[r0 + tid];
        int n = (int)(0xFFFFFFFFu - (unsigned)(p & 0xFFFFFFFFu));
        sidx[tid] = n;
        out[(size_t)BATCH * DDIM * TQ + r0 + tid] = (float)n;
    }
    __syncthreads();

    const int b = r0 / TQ;
    const int t0 = r0 % TQ;
    float* out_st = out;
    float* out_q  = out + (size_t)BATCH * DDIM * TQ + MROWS;

    for (int cc = 0; cc < DDIM; cc += 32) {
        #pragma unroll
        for (int i = 0; i < 4; i++) {
            int row = tyw + i * 8;
            tile[row][tx] = emb[(size_t)sidx[row] * DDIM + cc + tx];
        }
        __syncthreads();
        #pragma unroll
        for (int i = 0; i < 4; i++) {
            int cidx = cc + tyw + i * 8;
            size_t o = ((size_t)b * DDIM + cidx) * TQ + t0 + tx;
            float v = tile[tx][tyw + i * 8];
            out_q[o] = v;
            float zz = z[o];
            out_st[o] = zz + (v - zz);
        }
        __syncthreads();
    }
}

// ---------------- Launch ----------------
extern "C" void kernel_launch(void* const* d_in, const int* in_sizes, int n_in,
                              void* d_out, int out_size) {
    const float* z   = (const float*)d_in[0];   // [4, 512, 4096]
    const float* emb = (const float*)d_in[1];   // [8192, 512]
    float* out = (float*)d_out;

    init_flag_kernel<<<1, 1>>>();
    inv_norm_kernel<<<NCODES / 8, 256>>>(emb);
    conv_e_kernel<<<(NCODES * DDIM) / 256, 256>>>(emb);
    conv_z_kernel<<<dim3(TQ / 32, DDIM / 32, BATCH), 256>>>(z);

    gemm_argmax_kernel<<<dim3(NBLK, MROWS / BM), 256>>>();

    merge_flag_kernel<<<(MROWS * 32) / 256, 256>>>();
    fallback_kernel<<<512, 256>>>(z, emb);
    gather_kernel<<<MROWS / 32, 256>>>(z, emb, out);
}

// round 5
// speedup vs baseline: 5.9299x; 4.2935x over previous
#include <cuda_runtime.h>
#include <cuda_fp16.h>
#include <stdint.h>
#include <float.h>

// ---------------- Problem constants ----------------
#define BATCH   4
#define DDIM    512
#define TQ      4096
#define MROWS   (BATCH * TQ)      // 16384
#define NCODES  8192

// ---------------- GEMM tiling (int8) ----------------
#define BM 128
#define BN 128
#define BK 64                     // int8 elems per stage = 64 bytes/row
#define NBLK   (NCODES / BN)      // 64
#define NSTAGE (DDIM / BK)        // 8

#define ROWPITCH 80               // 64B data + 16B pad: ldsm conflict-free
#define AMAT  (128 * ROWPITCH)    // 10240
#define B_OFF AMAT
#define STAGE (2 * AMAT)          // 20480
#define SMEM_GEMM (2 * STAGE)     // 40960

// ---------------- Device scratch ----------------
__device__ float g_zt[(size_t)MROWS * DDIM];          // transposed z (fp32), 64MB
__device__ unsigned g_zq[(size_t)MROWS * DDIM / 4];   // int8 quantized z, 8MB
__device__ unsigned g_eq[(size_t)NCODES * DDIM / 4];  // int8 quantized e', 4MB
__device__ float g_sz[MROWS], g_P[MROWS];             // z scales + bound terms
__device__ float g_se[NCODES], g_Q[NCODES];           // e scales + bound terms
__device__ float g_inv_norm[NCODES];
__device__ __half g_up[(size_t)MROWS * NCODES];       // upper bounds, 256MB
__device__ unsigned g_maxlo[MROWS];                   // fkey(max lower bound)
__device__ unsigned long long g_best[MROWS];

// ---------------- helpers ----------------
__device__ __forceinline__ uint32_t smem_u32(const void* p) {
    uint32_t a;
    asm("{ .reg .u64 t; cvta.to.shared.u64 t, %1; cvt.u32.u64 %0, t; }" : "=r"(a) : "l"(p));
    return a;
}
__device__ __forceinline__ void cpasync16(uint32_t dst, const void* src) {
    asm volatile("cp.async.cg.shared.global [%0], [%1], 16;" :: "r"(dst), "l"(src) : "memory");
}
#define CP_COMMIT() asm volatile("cp.async.commit_group;" ::: "memory")
#define CP_WAIT(n)  asm volatile("cp.async.wait_group %0;" :: "n"(n) : "memory")

#define LDSM4(R, addr) \
    asm volatile("ldmatrix.sync.aligned.m8n8.x4.shared.b16 {%0,%1,%2,%3}, [%4];" \
                 : "=r"((R)[0]), "=r"((R)[1]), "=r"((R)[2]), "=r"((R)[3]) : "r"(addr))

#define MMA_S8(C, A, b0v, b1v) \
    asm volatile("mma.sync.aligned.m16n8k32.row.col.s32.s8.s8.s32 " \
                 "{%0,%1,%2,%3}, {%4,%5,%6,%7}, {%8,%9}, {%0,%1,%2,%3};" \
                 : "+r"((C)[0]), "+r"((C)[1]), "+r"((C)[2]), "+r"((C)[3]) \
                 : "r"((A)[0]), "r"((A)[1]), "r"((A)[2]), "r"((A)[3]), "r"(b0v), "r"(b1v))

__device__ __forceinline__ unsigned int fkey(float v) {
    unsigned int u = __float_as_uint(v);
    return (u & 0x80000000u) ? ~u : (u | 0x80000000u);
}
__device__ __forceinline__ float unkey(unsigned int k) {
    unsigned int u = (k & 0x80000000u) ? (k ^ 0x80000000u) : ~k;
    return __uint_as_float(u);
}
__device__ __forceinline__ unsigned long long pack_key(float v, int n) {
    return ((unsigned long long)fkey(v) << 32) | (unsigned long long)(0xFFFFFFFFu - (unsigned)n);
}

// ---------------- Small kernels ----------------
__global__ void init_maxlo_kernel() {
    int i = blockIdx.x * blockDim.x + threadIdx.x;
    if (i < MROWS) g_maxlo[i] = 0u;
}

__global__ void inv_norm_kernel(const float* __restrict__ emb) {
    int warp = (blockIdx.x * blockDim.x + threadIdx.x) >> 5;
    int lane = threadIdx.x & 31;
    if (warp >= NCODES) return;
    const float* row = emb + (size_t)warp * DDIM;
    float s = 0.f;
    #pragma unroll
    for (int k = lane; k < DDIM; k += 32) { float v = row[k]; s = fmaf(v, v, s); }
    #pragma unroll
    for (int o = 16; o; o >>= 1) s += __shfl_down_sync(0xffffffffu, s, o);
    if (lane == 0) g_inv_norm[warp] = 1.0f / fmaxf(sqrtf(s), 1e-12f);
}

// Transpose z: [b][k][t] -> z_t[m=b*TQ+t][k] fp32
__global__ __launch_bounds__(256) void transpose_z_kernel(const float* __restrict__ z) {
    __shared__ float tile[32][33];
    int b  = blockIdx.z;
    int k0 = blockIdx.y * 32;
    int t0 = blockIdx.x * 32;
    int tx = threadIdx.x & 31, ty = threadIdx.x >> 5;
    #pragma unroll
    for (int i = 0; i < 4; i++) {
        int kl = ty + i * 8;
        tile[kl][tx] = z[((size_t)b * DDIM + k0 + kl) * TQ + t0 + tx];
    }
    __syncthreads();
    #pragma unroll
    for (int i = 0; i < 4; i++) {
        int tl = ty + i * 8;
        int m = b * TQ + t0 + tl;
        g_zt[(size_t)m * DDIM + k0 + tx] = tile[tx][tl];
    }
}

// Generic per-row int8 quantizer: warp per row of 512 floats.
// src row -> qdst (packed), scale, bterm = 0.5*sum|q| + addc
template <int ADDC>
__global__ __launch_bounds__(256) void quant_kernel(const float* __restrict__ src,
                                                    unsigned* __restrict__ qdst,
                                                    float* __restrict__ scale,
                                                    float* __restrict__ bterm,
                                                    const float* __restrict__ rowscale) {
    int row = blockIdx.x * 8 + (threadIdx.x >> 5);
    int lane = threadIdx.x & 31;
    float rs = rowscale ? rowscale[row] : 1.0f;
    float v[16];
    const float4* sp = (const float4*)(src + (size_t)row * DDIM + lane * 16);
    #pragma unroll
    for (int j = 0; j < 4; j++) {
        float4 f = sp[j];
        v[j*4+0] = f.x * rs; v[j*4+1] = f.y * rs; v[j*4+2] = f.z * rs; v[j*4+3] = f.w * rs;
    }
    float amax = 0.f;
    #pragma unroll
    for (int j = 0; j < 16; j++) amax = fmaxf(amax, fabsf(v[j]));
    #pragma unroll
    for (int o = 16; o; o >>= 1) amax = fmaxf(amax, __shfl_xor_sync(0xffffffffu, amax, o));
    amax = fmaxf(amax, 1e-30f);
    float sc = amax / 127.0f;
    float inv = 127.0f / amax;
    int q[16], sabs = 0;
    #pragma unroll
    for (int j = 0; j < 16; j++) {
        int qq = __float2int_rn(v[j] * inv);
        qq = max(-127, min(127, qq));
        q[j] = qq;
        sabs += abs(qq);
    }
    #pragma unroll
    for (int o = 16; o; o >>= 1) sabs += __shfl_xor_sync(0xffffffffu, sabs, o);
    // pack 16 int8 -> 4 uints, store 16B
    unsigned w[4];
    #pragma unroll
    for (int g = 0; g < 4; g++)
        w[g] = (unsigned)(q[g*4] & 0xFF) | ((unsigned)(q[g*4+1] & 0xFF) << 8) |
               ((unsigned)(q[g*4+2] & 0xFF) << 16) | ((unsigned)(q[g*4+3] & 0xFF) << 24);
    uint4* dp = (uint4*)(qdst + (size_t)row * (DDIM / 4) + lane * 4);
    *dp = make_uint4(w[0], w[1], w[2], w[3]);
    if (lane == 0) {
        scale[row] = sc;
        bterm[row] = 0.5f * (float)sabs + (float)ADDC;
    }
}

// ---------------- int8 GEMM + bound epilogue ----------------
__device__ __forceinline__ void load_stage(uint32_t sbase, int tid, int m0, int n0, int k0) {
    #pragma unroll
    for (int it = 0; it < 2; it++) {
        int c = it * 256 + tid;
        int row = c >> 2, col = c & 3;
        cpasync16(sbase + (uint32_t)(row * ROWPITCH + col * 16),
                  (const char*)g_zq + (size_t)(m0 + row) * DDIM + k0 + col * 16);
    }
    #pragma unroll
    for (int it = 0; it < 2; it++) {
        int c = it * 256 + tid;
        int row = c >> 2, col = c & 3;
        cpasync16(sbase + B_OFF + (uint32_t)(row * ROWPITCH + col * 16),
                  (const char*)g_eq + (size_t)(n0 + row) * DDIM + k0 + col * 16);
    }
}

__global__ __launch_bounds__(256, 2)
void gemm_bound_kernel() {
    __shared__ char smem[SMEM_GEMM];
    __shared__ float s_sz[128], s_P[128], s_se[128], s_Q[128];
    __shared__ unsigned s_lo[128];
    uint32_t sb = smem_u32(smem);
    const int tid = threadIdx.x;
    const int w = tid >> 5, l = tid & 31;
    const int wy = w >> 2, wx = w & 3;
    const int m0 = blockIdx.y * BM;
    const int n0 = blockIdx.x * BN;

    if (tid < 128) {
        s_sz[tid] = g_sz[m0 + tid];
        s_P[tid]  = g_P[m0 + tid];
        s_se[tid] = g_se[n0 + tid];
        s_Q[tid]  = g_Q[n0 + tid];
        s_lo[tid] = 0u;
    }

    int c[4][4][4];
    #pragma unroll
    for (int i = 0; i < 4; i++)
        #pragma unroll
        for (int j = 0; j < 4; j++)
            #pragma unroll
            for (int r = 0; r < 4; r++) c[i][j][r] = 0;

    const uint32_t aBase = sb + (uint32_t)((wy * 64 + (l & 15)) * ROWPITCH + ((l >> 4) << 4));
    const uint32_t bBase = sb + B_OFF +
        (uint32_t)((wx * 32 + ((l >> 4) & 1) * 8 + (l & 7)) * ROWPITCH + ((l >> 3) & 1) * 16);

    load_stage(sb, tid, m0, n0, 0);
    CP_COMMIT();

    #pragma unroll 1
    for (int s = 0; s < NSTAGE; s++) {
        if (s > 0) __syncthreads();
        if (s + 1 < NSTAGE) {
            load_stage(sb + ((s + 1) & 1) * STAGE, tid, m0, n0, (s + 1) * BK);
            CP_COMMIT();
            CP_WAIT(1);
        } else {
            CP_WAIT(0);
        }
        __syncthreads();

        const uint32_t so = (uint32_t)((s & 1) * STAGE);
        #pragma unroll
        for (int ks = 0; ks < 2; ks++) {
            uint32_t ah[4][4];
            #pragma unroll
            for (int mi = 0; mi < 4; mi++)
                LDSM4(ah[mi], aBase + so + (uint32_t)(mi * 16 * ROWPITCH + ks * 32));
            uint32_t bh[2][4];
            #pragma unroll
            for (int np = 0; np < 2; np++)
                LDSM4(bh[np], bBase + so + (uint32_t)(np * 16 * ROWPITCH + ks * 32));
            #pragma unroll
            for (int mi = 0; mi < 4; mi++)
                #pragma unroll
                for (int ni = 0; ni < 4; ni++) {
                    int np = ni >> 1, q = (ni & 1) * 2;
                    MMA_S8(c[mi][ni], ah[mi], bh[np][q], bh[np][q + 1]);
                }
        }
    }

    // -------- epilogue: up/lo bounds --------
    #pragma unroll
    for (int mi = 0; mi < 4; mi++) {
        int rl = wy * 64 + mi * 16 + (l >> 2);
        float szl = s_sz[rl],     Pl = s_P[rl];
        float szh = s_sz[rl + 8], Ph = s_P[rl + 8];
        float lomax_l = -FLT_MAX, lomax_h = -FLT_MAX;
        #pragma unroll
        for (int ni = 0; ni < 4; ni++) {
            int ncol = wx * 32 + ni * 8 + 2 * (l & 3);
            float se0 = s_se[ncol], Q0 = s_Q[ncol];
            float se1 = s_se[ncol + 1], Q1 = s_Q[ncol + 1];
            float d00 = (float)c[mi][ni][0], d01 = (float)c[mi][ni][1];
            float d10 = (float)c[mi][ni][2], d11 = (float)c[mi][ni][3];
            float k00 = szl * se0, k01 = szl * se1, k10 = szh * se0, k11 = szh * se1;
            float b00 = Pl + Q0, b01 = Pl + Q1, b10 = Ph + Q0, b11 = Ph + Q1;
            float up00 = k00 * (d00 + b00), lo00 = k00 * (d00 - b00);
            float up01 = k01 * (d01 + b01), lo01 = k01 * (d01 - b01);
            float up10 = k10 * (d10 + b10), lo10 = k10 * (d10 - b10);
            float up11 = k11 * (d11 + b11), lo11 = k11 * (d11 - b11);
            __half2* pl = (__half2*)&g_up[(size_t)(m0 + rl) * NCODES + n0 + ncol];
            __half2* ph = (__half2*)&g_up[(size_t)(m0 + rl + 8) * NCODES + n0 + ncol];
            *pl = __halves2half2(__float2half_ru(up00), __float2half_ru(up01));
            *ph = __halves2half2(__float2half_ru(up10), __float2half_ru(up11));
            lomax_l = fmaxf(lomax_l, fmaxf(lo00, lo01));
            lomax_h = fmaxf(lomax_h, fmaxf(lo10, lo11));
        }
        atomicMax(&s_lo[rl], fkey(lomax_l));
        atomicMax(&s_lo[rl + 8], fkey(lomax_h));
    }
    __syncthreads();
    if (tid < 128) atomicMax(&g_maxlo[m0 + tid], s_lo[tid]);
}

// ---------------- Scan + exact fp32 rescore (warp per row) ----------------
__global__ __launch_bounds__(256)
void scan_rescore_kernel(const float* __restrict__ emb) {
    int m = blockIdx.x * 8 + (threadIdx.x >> 5);
    int lane = threadIdx.x & 31;
    const unsigned FULL = 0xffffffffu;

    float zr[16];
    const float* zrow = g_zt + (size_t)m * DDIM;
    #pragma unroll
    for (int i = 0; i < 16; i++) zr[i] = zrow[lane + 32 * i];

    float maxlo = unkey(g_maxlo[m]);
    unsigned long long best = 0ULL;

    const uint4* rowp = (const uint4*)(g_up + (size_t)m * NCODES);
    #pragma unroll 1
    for (int it = 0; it < 32; it++) {
        uint4 v = rowp[it * 32 + lane];
        unsigned mym = 0;
        const unsigned vv[4] = {v.x, v.y, v.z, v.w};
        #pragma unroll
        for (int p = 0; p < 4; p++) {
            float2 f = __half22float2(*(const __half2*)&vv[p]);
            if (f.x >= maxlo) mym |= 1u << (2 * p);
            if (f.y >= maxlo) mym |= 1u << (2 * p + 1);
        }
        unsigned act = __ballot_sync(FULL, mym != 0);
        while (act) {
            int src = __ffs(act) - 1;
            act &= act - 1;
            unsigned mm = __shfl_sync(FULL, mym, src);
            int nb = it * 256 + src * 8;
            while (mm) {
                int j = __ffs(mm) - 1;
                mm &= mm - 1;
                int n = nb + j;
                // exact fp32 rescore
                const float* er = emb + (size_t)n * DDIM;
                float s = 0.f;
                #pragma unroll
                for (int i = 0; i < 16; i++) s = fmaf(zr[i], er[lane + 32 * i], s);
                #pragma unroll
                for (int o = 16; o; o >>= 1) s += __shfl_xor_sync(FULL, s, o);
                s *= g_inv_norm[n];
                unsigned long long key = pack_key(s, n);
                if (key > best) best = key;
            }
        }
    }
    if (lane == 0) g_best[m] = best;
}

// ---------------- Gather + outputs ----------------
__global__ __launch_bounds__(256)
void gather_kernel(const float* __restrict__ z, const float* __restrict__ emb,
                   float* __restrict__ out) {
    __shared__ float tile[32][33];
    __shared__ int sidx[32];

    const int r0 = blockIdx.x * 32;
    const int tid = threadIdx.x;
    const int tx = tid & 31;
    const int tyw = tid >> 5;

    if (tid < 32) {
        unsigned long long p = g_best[r0 + tid];
        int n = (int)(0xFFFFFFFFu - (unsigned)(p & 0xFFFFFFFFu));
        sidx[tid] = n;
        out[(size_t)BATCH * DDIM * TQ + r0 + tid] = (float)n;
    }
    __syncthreads();

    const int b = r0 / TQ;
    const int t0 = r0 % TQ;
    float* out_st = out;
    float* out_q  = out + (size_t)BATCH * DDIM * TQ + MROWS;

    for (int cc = 0; cc < DDIM; cc += 32) {
        #pragma unroll
        for (int i = 0; i < 4; i++) {
            int row = tyw + i * 8;
            tile[row][tx] = emb[(size_t)sidx[row] * DDIM + cc + tx];
        }
        __syncthreads();
        #pragma unroll
        for (int i = 0; i < 4; i++) {
            int cidx = cc + tyw + i * 8;
            size_t o = ((size_t)b * DDIM + cidx) * TQ + t0 + tx;
            float v = tile[tx][tyw + i * 8];
            out_q[o] = v;
            float zz = z[o];
            out_st[o] = zz + (v - zz);
        }
        __syncthreads();
    }
}

// ---------------- Launch ----------------
extern "C" void kernel_launch(void* const* d_in, const int* in_sizes, int n_in,
                              void* d_out, int out_size) {
    const float* z   = (const float*)d_in[0];   // [4, 512, 4096]
    const float* emb = (const float*)d_in[1];   // [8192, 512]
    float* out = (float*)d_out;

    float* d_zt;
    cudaGetSymbolAddress((void**)&d_zt, g_zt);
    unsigned *d_zq, *d_eq;
    cudaGetSymbolAddress((void**)&d_zq, g_zq);
    cudaGetSymbolAddress((void**)&d_eq, g_eq);
    float *d_sz, *d_P, *d_se, *d_Q, *d_inv;
    cudaGetSymbolAddress((void**)&d_sz, g_sz);
    cudaGetSymbolAddress((void**)&d_P, g_P);
    cudaGetSymbolAddress((void**)&d_se, g_se);
    cudaGetSymbolAddress((void**)&d_Q, g_Q);
    cudaGetSymbolAddress((void**)&d_inv, g_inv_norm);

    init_maxlo_kernel<<<MROWS / 256, 256>>>();
    inv_norm_kernel<<<NCODES / 8, 256>>>(emb);
    // quantize codes (folding inv_norm): bound const 128
    quant_kernel<128><<<NCODES / 8, 256>>>(emb, d_eq, d_se, d_Q, d_inv);
    transpose_z_kernel<<<dim3(TQ / 32, DDIM / 32, BATCH), 256>>>(z);
    // quantize queries: bound const 128 folded into P (only once per pair needed;
    // pair bound = sz*se*(P + Q) with P = Sz/2 + 128, Q = Se/2)
    quant_kernel<128><<<MROWS / 8, 256>>>(d_zt, d_zq, d_sz, d_P, nullptr);

    gemm_bound_kernel<<<dim3(NBLK, MROWS / BM), 256>>>();

    scan_rescore_kernel<<<MROWS / 8, 256>>>(emb);
    gather_kernel<<<MROWS / 32, 256>>>(z, emb, out);
}